// round 1
// baseline (speedup 1.0000x reference)
#include <cuda_runtime.h>
#include <cuda_bf16.h>
#include <math.h>

#define H_DIM 768
#define T_TAGS 3
#define S_LEN 512
#define B_SZ 128
#define ROWS_PER_WARP 8

// -------------------- kernel 1: prediction = inputs @ W^T + b --------------------
__global__ __launch_bounds__(256) void pred_kernel(
    const float* __restrict__ x, const float* __restrict__ W,
    const float* __restrict__ bias, float* __restrict__ out, int nrows)
{
    __shared__ float4 ws[3 * (H_DIM / 4)];   // 576 float4 = 9 KB
    __shared__ float bs[3];
    for (int i = threadIdx.x; i < 3 * (H_DIM / 4); i += blockDim.x)
        ws[i] = reinterpret_cast<const float4*>(W)[i];
    if (threadIdx.x < 3) bs[threadIdx.x] = bias[threadIdx.x];
    __syncthreads();

    int gw   = (blockIdx.x * blockDim.x + threadIdx.x) >> 5;
    int lane = threadIdx.x & 31;
    int row0 = gw * ROWS_PER_WARP;

    for (int r = 0; r < ROWS_PER_WARP; r++) {
        int row = row0 + r;
        if (row >= nrows) break;
        const float4* xr = reinterpret_cast<const float4*>(x) + (size_t)row * (H_DIM / 4);
        float a0 = 0.f, a1 = 0.f, a2 = 0.f;
        #pragma unroll
        for (int i = 0; i < H_DIM / 128; i++) {       // 6 iters
            int idx = i * 32 + lane;
            float4 v  = xr[idx];
            float4 w0 = ws[idx];
            float4 w1 = ws[192 + idx];
            float4 w2 = ws[384 + idx];
            a0 = fmaf(v.x, w0.x, fmaf(v.y, w0.y, fmaf(v.z, w0.z, fmaf(v.w, w0.w, a0))));
            a1 = fmaf(v.x, w1.x, fmaf(v.y, w1.y, fmaf(v.z, w1.z, fmaf(v.w, w1.w, a1))));
            a2 = fmaf(v.x, w2.x, fmaf(v.y, w2.y, fmaf(v.z, w2.z, fmaf(v.w, w2.w, a2))));
        }
        #pragma unroll
        for (int off = 16; off; off >>= 1) {
            a0 += __shfl_xor_sync(0xffffffffu, a0, off);
            a1 += __shfl_xor_sync(0xffffffffu, a1, off);
            a2 += __shfl_xor_sync(0xffffffffu, a2, off);
        }
        if (lane == 0) {
            float* o = out + (size_t)row * 3;
            o[0] = a0 + bs[0];
            o[1] = a1 + bs[1];
            o[2] = a2 + bs[2];
        }
    }
}

// -------------------- CRF pieces --------------------
__device__ float g_part[B_SZ];

__device__ __forceinline__ float lse3(float x, float y, float z) {
    float m = fmaxf(x, fmaxf(y, z));
    return m + logf(expf(x - m) + expf(y - m) + expf(z - m));
}

// One block per batch element. Tree-reduce 512 3x3 log-semiring matrices.
__global__ __launch_bounds__(256) void crf_kernel(
    const float* __restrict__ pred, const void* __restrict__ yraw,
    const float* __restrict__ trans, const float* __restrict__ start_t,
    const float* __restrict__ stop_t)
{
    __shared__ float feats[S_LEN * 3];      // 6 KB
    __shared__ float mats[S_LEN * 9];       // 18 KB
    __shared__ float buf[256 * 9];          // 9 KB
    __shared__ float red[256];
    __shared__ float tr[9], st[3], sp[3];
    __shared__ int is64_s;

    int b   = blockIdx.x;
    int tid = threadIdx.x;

    if (tid < 9) tr[tid] = trans[tid];
    if (tid < 3) { st[tid] = start_t[tid]; sp[tid] = stop_t[tid]; }

    // Detect whether y is int64 or int32. Values are 0..2 (non-negative), so for
    // little-endian int64 every odd 32-bit word is 0. With int32 random tags the
    // probability all 16 odd words are 0 is 3^-16 (~2e-8).
    if (tid == 0) {
        const int* y32p = (const int*)yraw;
        int is64 = 1;
        #pragma unroll
        for (int k = 0; k < 16; k++)
            if (y32p[2 * k + 1] != 0) { is64 = 0; break; }
        is64_s = is64;
    }

    const float* pb = pred + (size_t)b * S_LEN * 3;
    for (int i = tid; i < S_LEN * 3; i += 256) feats[i] = pb[i];
    __syncthreads();

    const int is64 = is64_s;
    const long long* y64 = (const long long*)yraw + (size_t)b * S_LEN;
    const int*       y32 = (const int*)yraw       + (size_t)b * S_LEN;
    #define TAG(s) (is64 ? (int)y64[(s)] : y32[(s)])

    // ---- gold path score ----
    float acc = 0.f;
    for (int s = tid; s < S_LEN; s += 256) {
        int tg = TAG(s);
        acc += feats[s * 3 + tg];
        if (s > 0) { int tp = TAG(s - 1); acc += tr[tp * 3 + tg]; }
    }
    if (tid == 0) acc += st[TAG(0)] + sp[TAG(S_LEN - 1)];
    red[tid] = acc;
    __syncthreads();
    for (int h = 128; h; h >>= 1) {
        if (tid < h) red[tid] += red[tid + h];
        __syncthreads();
    }
    float seq_score = red[0];

    // ---- build 512 log-semiring matrices ----
    // M_0[i][j] = a0[j] = feats[0][j] + start[j]   (rank-1: every row identical)
    // M_t[i][j] = trans[i][j] + feats[t][j]        (t = 1..511)
    for (int i = tid; i < S_LEN * 9; i += 256) {
        int t = i / 9, e = i % 9, col = e % 3;
        mats[i] = (t == 0) ? (feats[col] + st[col]) : (tr[e] + feats[t * 3 + col]);
    }
    __syncthreads();

    // ---- tree reduction (order-preserving pairwise product) ----
    float* src = mats;
    float* dst = buf;
    int n = S_LEN;
    while (n > 1) {
        int half = n >> 1;
        if (tid < half) {
            const float* A  = src + (size_t)(2 * tid) * 9;
            const float* Bm = src + (size_t)(2 * tid + 1) * 9;
            float c[9];
            #pragma unroll
            for (int i2 = 0; i2 < 3; i2++)
                #pragma unroll
                for (int j = 0; j < 3; j++)
                    c[i2 * 3 + j] = lse3(A[i2 * 3 + 0] + Bm[0 * 3 + j],
                                         A[i2 * 3 + 1] + Bm[1 * 3 + j],
                                         A[i2 * 3 + 2] + Bm[2 * 3 + j]);
            #pragma unroll
            for (int e = 0; e < 9; e++) dst[tid * 9 + e] = c[e];
        }
        __syncthreads();
        float* tmp = src; src = dst; dst = tmp;
        n = half;
    }

    if (tid == 0) {
        // row 0 of the final product is a_T
        float logz = lse3(src[0] + sp[0], src[1] + sp[1], src[2] + sp[2]);
        g_part[b] = seq_score - logz;
    }
    #undef TAG
}

// -------------------- kernel 3: mean-reduce 128 partials --------------------
__global__ void finalize_kernel(float* loss_out) {
    __shared__ float red[B_SZ];
    int tid = threadIdx.x;
    red[tid] = g_part[tid];
    __syncthreads();
    for (int h = B_SZ / 2; h; h >>= 1) {
        if (tid < h) red[tid] += red[tid + h];
        __syncthreads();
    }
    if (tid == 0) *loss_out = -red[0] / (float)B_SZ;
}

// -------------------- launch --------------------
extern "C" void kernel_launch(void* const* d_in, const int* in_sizes, int n_in,
                              void* d_out, int out_size)
{
    const float* x     = (const float*)d_in[0];
    const void*  y     = d_in[1];
    const float* W     = (const float*)d_in[2];
    const float* bias  = (const float*)d_in[3];
    const float* trans = (const float*)d_in[4];
    const float* st    = (const float*)d_in[5];
    const float* sp    = (const float*)d_in[6];
    float* out = (float*)d_out;

    int nrows = in_sizes[0] / H_DIM;                       // 65536
    int warps = (nrows + ROWS_PER_WARP - 1) / ROWS_PER_WARP;
    int blocks = (warps * 32 + 255) / 256;

    pred_kernel<<<blocks, 256>>>(x, W, bias, out, nrows);
    crf_kernel<<<B_SZ, 256>>>(out, y, trans, st, sp);
    finalize_kernel<<<1, B_SZ>>>(out + (out_size - 1));
}